// round 16
// baseline (speedup 1.0000x reference)
#include <cuda_runtime.h>
#include <math.h>
#include <stdint.h>

#define T_TOK 2048
#define H_DIM 1024
#define F_DIM 4096
#define E_NUM 8
#define STAGES 3
#define MAX_TILES 40   // sum ceil(cnt_e/128) <= 4096/128 + 8 = 40
#define KSPLIT2 2      // mlp2 split-K factor
#define NPROD (64 * MAX_TILES)          // 2560 producer CTAs
#define NCONS (8 * MAX_TILES * KSPLIT2) // 640 consumer CTAs

// ---------------- scratch (static device globals; allocation-free) ----------------
__device__ float g_xc [(size_t)T_TOK*H_DIM];          // tf32-rna pre-rounded x
__device__ float g_act[(size_t)(T_TOK*2+256)*F_DIM];  // tf32-rna rounded activations
__device__ int   g_list[E_NUM*T_TOK];
__device__ float g_wgt [E_NUM*T_TOK];
__device__ int   g_cnt[E_NUM];
__device__ int   g_off[E_NUM];
__device__ int   g_tidx[T_TOK*2];
__device__ float g_tw  [T_TOK*2];
__device__ int   g_te[MAX_TILES];
__device__ int   g_tm[MAX_TILES];
__device__ int   g_ntiles;
__device__ int   g_done[MAX_TILES];     // per-tile producer completion counters

// ---------------- helpers ----------------
__device__ __forceinline__ float to_tf32(float x) {
    unsigned u;
    asm("cvt.rna.tf32.f32 %0, %1;" : "=r"(u) : "f"(x));
    return __uint_as_float(u);
}
__device__ __forceinline__ uint32_t cvt_frag(uint32_t v) {
    unsigned u;
    asm("cvt.rna.tf32.f32 %0, %1;" : "=r"(u) : "f"(__uint_as_float(v)));
    return u;
}
__device__ __forceinline__ float gelu_exact(float v) {
    return 0.5f * v * (1.0f + erff(v * 0.70710678118654752440f));
}
__device__ __forceinline__ uint32_t smem_u32(const void* p) {
    uint32_t a;
    asm("{ .reg .u64 t; cvta.to.shared.u64 t, %1; cvt.u32.u64 %0, t; }" : "=r"(a) : "l"(p));
    return a;
}
__device__ __forceinline__ void cp_async16(uint32_t smem_dst, const void* gmem_src) {
    asm volatile("cp.async.cg.shared.global [%0], [%1], 16;\n" :: "r"(smem_dst), "l"(gmem_src));
}
#define CP_COMMIT() asm volatile("cp.async.commit_group;\n")
#define CP_WAIT(n)  asm volatile("cp.async.wait_group %0;\n" :: "n"(n))

// tf32 mma with raw u32 fragments (operands rna-pre-rounded)
__device__ __forceinline__ void mma_tf32(float* c, const uint32_t* a, const uint32_t* b) {
    asm volatile(
        "mma.sync.aligned.m16n8k8.row.col.f32.tf32.tf32.f32 "
        "{%0,%1,%2,%3}, {%4,%5,%6,%7}, {%8,%9}, {%0,%1,%2,%3};\n"
        : "+f"(c[0]), "+f"(c[1]), "+f"(c[2]), "+f"(c[3])
        : "r"(a[0]), "r"(a[1]), "r"(a[2]), "r"(a[3]), "r"(b[0]), "r"(b[1]));
}

// ldmatrix x4 on 32-bit data: 8x8 b16 tile == 8x4 float tile.
__device__ __forceinline__ void ldsm_x4(uint32_t addr, uint32_t* r) {
    asm volatile("ldmatrix.sync.aligned.m8n8.x4.shared.b16 {%0,%1,%2,%3}, [%4];"
        : "=r"(r[0]), "=r"(r[1]), "=r"(r[2]), "=r"(r[3]) : "r"(addr));
}

// ---------------- small kernels ----------------
// router + fused tf32-rna rounding of x into g_xc + fused zeroing of out
__global__ void router_kernel(const float* __restrict__ x, const float* __restrict__ gw,
                              float4* __restrict__ outz) {
    int tid = threadIdx.x;
    {
        int gidx = blockIdx.x * blockDim.x + tid;
        const float4 z = make_float4(0.f, 0.f, 0.f, 0.f);
#pragma unroll
        for (int i = 0; i < 8; i++)
            outz[gidx + i * 65536] = z;
    }

    int warp = (blockIdx.x * blockDim.x + tid) >> 5;
    int lane = tid & 31;
    if (warp >= T_TOK) return;
    float acc[E_NUM];
#pragma unroll
    for (int e = 0; e < E_NUM; e++) acc[e] = 0.f;
    const float* xr = x + (size_t)warp * H_DIM;
    float* xo = g_xc + (size_t)warp * H_DIM;
    for (int h = lane; h < H_DIM; h += 32) {
        float xv = xr[h];
        xo[h] = to_tf32(xv);
#pragma unroll
        for (int e = 0; e < E_NUM; e++) acc[e] += xv * gw[e * H_DIM + h];
    }
#pragma unroll
    for (int e = 0; e < E_NUM; e++) {
#pragma unroll
        for (int o = 16; o > 0; o >>= 1) acc[e] += __shfl_xor_sync(0xffffffffu, acc[e], o);
    }
    if (lane == 0) {
        float p[E_NUM], mx = -1e30f;
#pragma unroll
        for (int e = 0; e < E_NUM; e++) {
            p[e] = 30.0f * tanhf(acc[e] * (1.0f / 30.0f));
            mx = fmaxf(mx, p[e]);
        }
        float s = 0.f;
#pragma unroll
        for (int e = 0; e < E_NUM; e++) { p[e] = expf(p[e] - mx); s += p[e]; }
        int i0 = 0;
#pragma unroll
        for (int e = 1; e < E_NUM; e++) if (p[e] > p[i0]) i0 = e;
        int i1 = (i0 == 0) ? 1 : 0;
#pragma unroll
        for (int e = 0; e < E_NUM; e++) if (e != i0 && p[e] > p[i1]) i1 = e;
        float inv = 1.0f / s;
        g_tidx[warp * 2 + 0] = i0;  g_tw[warp * 2 + 0] = p[i0] * inv;
        g_tidx[warp * 2 + 1] = i1;  g_tw[warp * 2 + 1] = p[i1] * inv;
    }
}

__global__ void build_kernel() {
    int e    = threadIdx.x >> 5;
    int lane = threadIdx.x & 31;
    if (threadIdx.x < MAX_TILES) g_done[threadIdx.x] = 0;   // reset dataflow counters
    int cnt  = 0;
    for (int base = 0; base < T_TOK; base += 32) {
        int t = base + lane;
        int i0 = g_tidx[t * 2], i1 = g_tidx[t * 2 + 1];
        bool hit = (i0 == e) || (i1 == e);
        float w = (i0 == e) ? g_tw[t * 2] : g_tw[t * 2 + 1];
        unsigned mask = __ballot_sync(0xffffffffu, hit);
        if (hit) {
            int pos = cnt + __popc(mask & ((1u << lane) - 1u));
            g_list[e * T_TOK + pos] = t;
            g_wgt [e * T_TOK + pos] = w;
        }
        cnt += __popc(mask);
    }
    if (lane == 0) g_cnt[e] = cnt;
    __syncthreads();
    if (threadIdx.x == 0) {
        int off = 0, nt = 0;
        for (int ee = 0; ee < E_NUM; ee++) { g_off[ee] = off; off += g_cnt[ee]; }
        for (int ee = 0; ee < E_NUM; ee++)
            for (int m0 = 0; m0 < g_cnt[ee]; m0 += 128) {
                g_te[nt] = ee; g_tm[nt] = m0; nt++;
            }
        g_ntiles = nt;
    }
}

// ---------------- fused GEMM kernel ----------------
#define S1_A   4608                 // 128*36 floats
#define S1_B   2304                 // 64*36 floats
#define S1_TOT (S1_A + 2 * S1_B)    // 9216 floats
#define S2_A   4608
#define S2_B   4608
#define S2_TOT (S2_A + S2_B)        // 9216 floats

extern __shared__ float dynsm[];

__device__ __forceinline__ void load1(uint32_t sbase, int buf, int k0,
                                      const float* __restrict__ w1e,
                                      const float* __restrict__ w3e,
                                      const int* ls, int tid) {
    uint32_t sA  = sbase + (uint32_t)buf * S1_TOT * 4;
    uint32_t sB1 = sA + S1_A * 4;
    uint32_t sB3 = sB1 + S1_B * 4;
#pragma unroll
    for (int t = 0; t < 4; t++) {
        int idx = tid + t * 256;
        int r = idx >> 3, c4 = (idx & 7) * 4;
        cp_async16(sA + (r * 36 + c4) * 4, g_xc + (size_t)ls[r] * H_DIM + k0 + c4);
    }
#pragma unroll
    for (int t = 0; t < 2; t++) {
        int idx = tid + t * 256;
        int r = idx >> 3, c4 = (idx & 7) * 4;
        cp_async16(sB1 + (r * 36 + c4) * 4, w1e + (size_t)r * H_DIM + k0 + c4);
        cp_async16(sB3 + (r * 36 + c4) * 4, w3e + (size_t)r * H_DIM + k0 + c4);
    }
}

__device__ __forceinline__ void load2(uint32_t sbase, int buf, int k0,
                                      const float* __restrict__ arow,
                                      const float* __restrict__ w2e, int tid) {
    uint32_t sA = sbase + (uint32_t)buf * S2_TOT * 4;
    uint32_t sB = sA + S2_A * 4;
#pragma unroll
    for (int t = 0; t < 4; t++) {
        int idx = tid + t * 256;
        int r = idx >> 3, c4 = (idx & 7) * 4;
        cp_async16(sA + (r * 36 + c4) * 4, arow + (size_t)r * F_DIM + k0 + c4);
        cp_async16(sB + (r * 36 + c4) * 4, w2e  + (size_t)r * F_DIM + k0 + c4);
    }
}

__global__ __launch_bounds__(256, 2) void moe_kernel(
        const float* __restrict__ w1, const float* __restrict__ w3,
        const float* __restrict__ w2, float* __restrict__ out) {
    __shared__ int   ls[128];
    __shared__ float ws[128];

    int tid = threadIdx.x, lane = tid & 31, wid = tid >> 5;
    int wm = wid >> 2, wn = wid & 3;          // 2(M) x 4(N)
    uint32_t sbase = smem_u32(dynsm);
    int lrow = lane & 7, lt = lane >> 3;

    if (blockIdx.x < NPROD) {
        // =================== producer: mlp1 ===================
        int tidx = blockIdx.x >> 6;            // tile
        int f0   = (blockIdx.x & 63) * 64;
        if (tidx >= g_ntiles) return;
        int e   = g_te[tidx];
        int m0  = g_tm[tidx];
        int cnt = g_cnt[e];
        int off = g_off[e];

        if (tid < 128) {
            int gm = m0 + tid;
            ls[tid] = (gm < cnt) ? g_list[e * T_TOK + gm] : 0;
            ws[tid] = (gm < cnt) ? g_wgt [e * T_TOK + gm] : 0.f;
        }
        __syncthreads();

        uint32_t aoff[4], boff[2];
#pragma unroll
        for (int mt = 0; mt < 4; mt++)
            aoff[mt] = ((wm * 64 + mt * 16 + (lt & 1) * 8 + lrow) * 36 + (lt >> 1) * 4) * 4;
#pragma unroll
        for (int nt = 0; nt < 2; nt++)
            boff[nt] = ((wn * 16 + nt * 8 + lrow) * 36 + lt * 4) * 4;

        float accG[4][2][4], accU[4][2][4];
#pragma unroll
        for (int i = 0; i < 4; i++)
#pragma unroll
            for (int j = 0; j < 2; j++)
#pragma unroll
                for (int k = 0; k < 4; k++) { accG[i][j][k] = 0.f; accU[i][j][k] = 0.f; }

        const float* w1e = w1 + ((size_t)e * F_DIM + f0) * H_DIM;
        const float* w3e = w3 + ((size_t)e * F_DIM + f0) * H_DIM;

        const int NT = H_DIM / 32;   // 32
#pragma unroll
        for (int s = 0; s < STAGES - 1; s++) {
            load1(sbase, s, s * 32, w1e, w3e, ls, tid);
            CP_COMMIT();
        }

        int cbuf = 0, pbuf = STAGES - 1;
        for (int kt = 0; kt < NT; kt++) {
            CP_WAIT(STAGES - 2);
            __syncthreads();
            int nxt = kt + STAGES - 1;
            if (nxt < NT) load1(sbase, pbuf, nxt * 32, w1e, w3e, ls, tid);
            CP_COMMIT();
            if (++pbuf == STAGES) pbuf = 0;

            uint32_t sA  = sbase + (uint32_t)cbuf * S1_TOT * 4;
            uint32_t sB1 = sA + S1_A * 4;
            uint32_t sB3 = sB1 + S1_B * 4;
            if (++cbuf == STAGES) cbuf = 0;

#pragma unroll
            for (int p = 0; p < 2; p++) {
                uint32_t b1f[2][4], b3f[2][4];
#pragma unroll
                for (int nt = 0; nt < 2; nt++) {
                    ldsm_x4(sB1 + boff[nt] + p * 64, b1f[nt]);
                    ldsm_x4(sB3 + boff[nt] + p * 64, b3f[nt]);
#pragma unroll
                    for (int j = 0; j < 4; j++) {
                        b1f[nt][j] = cvt_frag(b1f[nt][j]);
                        b3f[nt][j] = cvt_frag(b3f[nt][j]);
                    }
                }
#pragma unroll
                for (int kq = 0; kq < 2; kq++) {
#pragma unroll
                    for (int mt = 0; mt < 4; mt++) {
                        uint32_t af[4];
                        ldsm_x4(sA + aoff[mt] + (p * 2 + kq) * 32, af);
#pragma unroll
                        for (int nt = 0; nt < 2; nt++) {
                            mma_tf32(accG[mt][nt], af, b1f[nt] + kq * 2);
                            mma_tf32(accU[mt][nt], af, b3f[nt] + kq * 2);
                        }
                    }
                }
            }
        }

        // epilogue: act = tf32( weight * gelu(G) * U )
#pragma unroll
        for (int mt = 0; mt < 4; mt++) {
            int rbase = wm * 64 + mt * 16 + (lane >> 2);
#pragma unroll
            for (int half = 0; half < 2; half++) {
                int m = rbase + half * 8;
                if (m0 + m >= cnt) continue;
                float wgt = ws[m];
                size_t rowoff = (size_t)(off + m0 + m) * F_DIM;
#pragma unroll
                for (int nt = 0; nt < 2; nt++) {
                    int col = f0 + wn * 16 + nt * 8 + (lane & 3) * 2;
                    float2 o;
                    o.x = to_tf32(wgt * accU[mt][nt][half*2+0] * gelu_exact(accG[mt][nt][half*2+0]));
                    o.y = to_tf32(wgt * accU[mt][nt][half*2+1] * gelu_exact(accG[mt][nt][half*2+1]));
                    *reinterpret_cast<float2*>(&g_act[rowoff + col]) = o;
                }
            }
        }

        // dataflow signal: this (tile, f-block) is complete
        __threadfence();
        __syncthreads();
        if (tid == 0) atomicAdd(&g_done[tidx], 1);
        return;
    }

    // =================== consumer: mlp2 ===================
    {
        int cbid = blockIdx.x - NPROD;         // [0, 640)
        int h0   = (cbid & 7) * 128;
        int r    = cbid >> 3;
        int tidx = r % MAX_TILES;
        int kp   = r / MAX_TILES;
        if (tidx >= g_ntiles) return;
        int e   = g_te[tidx];
        int m0  = g_tm[tidx];
        int cnt = g_cnt[e];
        int off = g_off[e];
        int kbase = kp * (F_DIM / KSPLIT2);

        // wait for all 64 producer f-blocks of this tile
        if (tid == 0) {
            while (atomicAdd(&g_done[tidx], 0) < 64)
                __nanosleep(128);
        }
        __syncthreads();
        __threadfence();   // acquire: order subsequent act reads after counter observation

        if (tid < 128) {
            int gm = m0 + tid;
            ls[tid] = (gm < cnt) ? g_list[e * T_TOK + gm] : 0;
        }
        __syncthreads();

        uint32_t aoff[4], boff[4];
#pragma unroll
        for (int mt = 0; mt < 4; mt++)
            aoff[mt] = ((wm * 64 + mt * 16 + (lt & 1) * 8 + lrow) * 36 + (lt >> 1) * 4) * 4;
#pragma unroll
        for (int nt = 0; nt < 4; nt++)
            boff[nt] = ((wn * 32 + nt * 8 + lrow) * 36 + lt * 4) * 4;

        float acc[4][4][4];
#pragma unroll
        for (int i = 0; i < 4; i++)
#pragma unroll
            for (int j = 0; j < 4; j++)
#pragma unroll
                for (int k = 0; k < 4; k++) acc[i][j][k] = 0.f;

        const float* w2e  = w2 + ((size_t)e * H_DIM + h0) * F_DIM + kbase;
        const float* arow = g_act + (size_t)(off + m0) * F_DIM + kbase;

        const int NT = F_DIM / (32 * KSPLIT2);   // 64
#pragma unroll
        for (int s = 0; s < STAGES - 1; s++) {
            load2(sbase, s, s * 32, arow, w2e, tid);
            CP_COMMIT();
        }

        int cbuf = 0, pbuf = STAGES - 1;
        for (int kt = 0; kt < NT; kt++) {
            CP_WAIT(STAGES - 2);
            __syncthreads();
            int nxt = kt + STAGES - 1;
            if (nxt < NT) load2(sbase, pbuf, nxt * 32, arow, w2e, tid);
            CP_COMMIT();
            if (++pbuf == STAGES) pbuf = 0;

            uint32_t sA = sbase + (uint32_t)cbuf * S2_TOT * 4;
            uint32_t sB = sA + S2_A * 4;
            if (++cbuf == STAGES) cbuf = 0;

#pragma unroll
            for (int p = 0; p < 2; p++) {
                uint32_t bf[4][4];
#pragma unroll
                for (int nt = 0; nt < 4; nt++) {
                    ldsm_x4(sB + boff[nt] + p * 64, bf[nt]);
#pragma unroll
                    for (int j = 0; j < 4; j++) bf[nt][j] = cvt_frag(bf[nt][j]);
                }
#pragma unroll
                for (int kq = 0; kq < 2; kq++) {
#pragma unroll
                    for (int mt = 0; mt < 4; mt++) {
                        uint32_t af[4];
                        ldsm_x4(sA + aoff[mt] + (p * 2 + kq) * 32, af);
#pragma unroll
                        for (int nt = 0; nt < 4; nt++)
                            mma_tf32(acc[mt][nt], af, bf[nt] + kq * 2);
                    }
                }
            }
        }

        // epilogue: atomicAdd into out (commutative fp32 adds; <=4 contributions/element)
#pragma unroll
        for (int mt = 0; mt < 4; mt++) {
            int rbase = wm * 64 + mt * 16 + (lane >> 2);
#pragma unroll
            for (int half = 0; half < 2; half++) {
                int m = rbase + half * 8;
                if (m0 + m >= cnt) continue;
                int token = ls[m];
#pragma unroll
                for (int nt = 0; nt < 4; nt++) {
                    int h = h0 + wn * 32 + nt * 8 + (lane & 3) * 2;
                    atomicAdd(&out[(size_t)token * H_DIM + h],     acc[mt][nt][half * 2 + 0]);
                    atomicAdd(&out[(size_t)token * H_DIM + h + 1], acc[mt][nt][half * 2 + 1]);
                }
            }
        }
    }
}

// ---------------- launch ----------------
extern "C" void kernel_launch(void* const* d_in, const int* in_sizes, int n_in,
                              void* d_out, int out_size) {
    const float* x  = (const float*)d_in[0];   // [T, H]
    const float* gw = (const float*)d_in[1];   // [E, H]
    const float* w1 = (const float*)d_in[2];   // [E, F, H]
    const float* w2 = (const float*)d_in[3];   // [E, H, F]
    const float* w3 = (const float*)d_in[4];   // [E, F, H]
    float* out = (float*)d_out;                // [T, H]

    const int smem = STAGES * S1_TOT * 4;   // 110592 B (S1_TOT == S2_TOT)
    cudaFuncSetAttribute(moe_kernel, cudaFuncAttributeMaxDynamicSharedMemorySize, smem);

    // router also zeroes out and writes rounded x -> g_xc
    router_kernel<<<T_TOK / 8, 256>>>(x, gw, (float4*)out);
    build_kernel<<<1, 256>>>();                 // also builds tile list + resets g_done

    moe_kernel<<<NPROD + NCONS, 256, smem>>>(w1, w3, w2, out);
}

// round 17
// speedup vs baseline: 1.0160x; 1.0160x over previous
#include <cuda_runtime.h>
#include <math.h>
#include <stdint.h>

#define T_TOK 2048
#define H_DIM 1024
#define F_DIM 4096
#define E_NUM 8
#define STAGES 3
#define MAX_TILES 40   // sum ceil(cnt_e/128) <= 4096/128 + 8 = 40
#define KSPLIT2 2      // mlp2 split-K factor

// ---------------- scratch (static device globals; allocation-free) ----------------
__device__ float g_xc [(size_t)T_TOK*H_DIM];          // tf32-rna pre-rounded x
__device__ float g_act[(size_t)(T_TOK*2+256)*F_DIM];  // tf32-rna rounded activations
__device__ int   g_list[E_NUM*T_TOK];
__device__ float g_wgt [E_NUM*T_TOK];
__device__ int   g_cnt[E_NUM];
__device__ int   g_off[E_NUM];
__device__ int   g_tidx[T_TOK*2];
__device__ float g_tw  [T_TOK*2];
__device__ int   g_te[MAX_TILES];
__device__ int   g_tm[MAX_TILES];
__device__ int   g_ntiles;

// ---------------- helpers ----------------
__device__ __forceinline__ float to_tf32(float x) {
    unsigned u;
    asm("cvt.rna.tf32.f32 %0, %1;" : "=r"(u) : "f"(x));
    return __uint_as_float(u);
}
__device__ __forceinline__ uint32_t cvt_frag(uint32_t v) {
    unsigned u;
    asm("cvt.rna.tf32.f32 %0, %1;" : "=r"(u) : "f"(__uint_as_float(v)));
    return u;
}
__device__ __forceinline__ float gelu_exact(float v) {
    return 0.5f * v * (1.0f + erff(v * 0.70710678118654752440f));
}
__device__ __forceinline__ uint32_t smem_u32(const void* p) {
    uint32_t a;
    asm("{ .reg .u64 t; cvta.to.shared.u64 t, %1; cvt.u32.u64 %0, t; }" : "=r"(a) : "l"(p));
    return a;
}
__device__ __forceinline__ void cp_async16(uint32_t smem_dst, const void* gmem_src) {
    asm volatile("cp.async.cg.shared.global [%0], [%1], 16;\n" :: "r"(smem_dst), "l"(gmem_src));
}
#define CP_COMMIT() asm volatile("cp.async.commit_group;\n")
#define CP_WAIT(n)  asm volatile("cp.async.wait_group %0;\n" :: "n"(n))

// tf32 mma with raw u32 fragments (operands rna-pre-rounded)
__device__ __forceinline__ void mma_tf32(float* c, const uint32_t* a, const uint32_t* b) {
    asm volatile(
        "mma.sync.aligned.m16n8k8.row.col.f32.tf32.tf32.f32 "
        "{%0,%1,%2,%3}, {%4,%5,%6,%7}, {%8,%9}, {%0,%1,%2,%3};\n"
        : "+f"(c[0]), "+f"(c[1]), "+f"(c[2]), "+f"(c[3])
        : "r"(a[0]), "r"(a[1]), "r"(a[2]), "r"(a[3]), "r"(b[0]), "r"(b[1]));
}

// ldmatrix x4 on 32-bit data: 8x8 b16 tile == 8x4 float tile.
__device__ __forceinline__ void ldsm_x4(uint32_t addr, uint32_t* r) {
    asm volatile("ldmatrix.sync.aligned.m8n8.x4.shared.b16 {%0,%1,%2,%3}, [%4];"
        : "=r"(r[0]), "=r"(r[1]), "=r"(r[2]), "=r"(r[3]) : "r"(addr));
}

// ---------------- small kernels ----------------
// router (float4-vectorized) + fused tf32-rna rounding of x + fused zeroing of out.
// 512 blocks x 128 threads; warp per token.
__global__ void router_kernel(const float4* __restrict__ x4, const float4* __restrict__ gw4,
                              float4* __restrict__ outz) {
    int tid = threadIdx.x;
    int gidx = blockIdx.x * 128 + tid;         // 0..65535
    {
        const float4 z = make_float4(0.f, 0.f, 0.f, 0.f);
#pragma unroll
        for (int i = 0; i < 8; i++)
            outz[gidx + i * 65536] = z;
    }

    int warp = gidx >> 5;                      // token
    int lane = tid & 31;
    float acc[E_NUM];
#pragma unroll
    for (int e = 0; e < E_NUM; e++) acc[e] = 0.f;

    const float4* xr = x4 + (size_t)warp * (H_DIM / 4);
    float4* xo = (float4*)g_xc + (size_t)warp * (H_DIM / 4);
#pragma unroll
    for (int i = 0; i < 8; i++) {
        int h4 = i * 32 + lane;                // float4 index within row (0..255)
        float4 v = xr[h4];
        xo[h4] = make_float4(to_tf32(v.x), to_tf32(v.y), to_tf32(v.z), to_tf32(v.w));
#pragma unroll
        for (int e = 0; e < E_NUM; e++) {
            float4 g = gw4[e * (H_DIM / 4) + h4];
            acc[e] += v.x * g.x + v.y * g.y + v.z * g.z + v.w * g.w;
        }
    }
#pragma unroll
    for (int e = 0; e < E_NUM; e++) {
#pragma unroll
        for (int o = 16; o > 0; o >>= 1) acc[e] += __shfl_xor_sync(0xffffffffu, acc[e], o);
    }
    if (lane == 0) {
        float p[E_NUM], mx = -1e30f;
#pragma unroll
        for (int e = 0; e < E_NUM; e++) {
            p[e] = 30.0f * tanhf(acc[e] * (1.0f / 30.0f));
            mx = fmaxf(mx, p[e]);
        }
        float s = 0.f;
#pragma unroll
        for (int e = 0; e < E_NUM; e++) { p[e] = expf(p[e] - mx); s += p[e]; }
        int i0 = 0;
#pragma unroll
        for (int e = 1; e < E_NUM; e++) if (p[e] > p[i0]) i0 = e;
        int i1 = (i0 == 0) ? 1 : 0;
#pragma unroll
        for (int e = 0; e < E_NUM; e++) if (e != i0 && p[e] > p[i1]) i1 = e;
        float inv = 1.0f / s;
        g_tidx[warp * 2 + 0] = i0;  g_tw[warp * 2 + 0] = p[i0] * inv;
        g_tidx[warp * 2 + 1] = i1;  g_tw[warp * 2 + 1] = p[i1] * inv;
    }
}

__global__ void build_kernel() {
    int e    = threadIdx.x >> 5;
    int lane = threadIdx.x & 31;
    int cnt  = 0;
    for (int base = 0; base < T_TOK; base += 32) {
        int t = base + lane;
        int i0 = g_tidx[t * 2], i1 = g_tidx[t * 2 + 1];
        bool hit = (i0 == e) || (i1 == e);
        float w = (i0 == e) ? g_tw[t * 2] : g_tw[t * 2 + 1];
        unsigned mask = __ballot_sync(0xffffffffu, hit);
        if (hit) {
            int pos = cnt + __popc(mask & ((1u << lane) - 1u));
            g_list[e * T_TOK + pos] = t;
            g_wgt [e * T_TOK + pos] = w;
        }
        cnt += __popc(mask);
    }
    if (lane == 0) g_cnt[e] = cnt;
    __syncthreads();
    if (threadIdx.x == 0) {
        int off = 0, nt = 0;
        for (int ee = 0; ee < E_NUM; ee++) { g_off[ee] = off; off += g_cnt[ee]; }
        for (int ee = 0; ee < E_NUM; ee++)
            for (int m0 = 0; m0 < g_cnt[ee]; m0 += 128) {
                g_te[nt] = ee; g_tm[nt] = m0; nt++;
            }
        g_ntiles = nt;
    }
}

// ---------------- GEMM1: M=128 N=64(x2 mats), warps 2(M)x4(N), warp tile 64x16/mat ----
#define S1_A   4608                 // 128*36 floats
#define S1_B   2304                 // 64*36 floats
#define S1_TOT (S1_A + 2 * S1_B)    // 9216 floats

extern __shared__ float dynsm[];

__device__ __forceinline__ void load1(uint32_t sbase, int buf, int k0,
                                      const float* __restrict__ w1e,
                                      const float* __restrict__ w3e,
                                      const int* ls, int tid) {
    uint32_t sA  = sbase + (uint32_t)buf * S1_TOT * 4;
    uint32_t sB1 = sA + S1_A * 4;
    uint32_t sB3 = sB1 + S1_B * 4;
#pragma unroll
    for (int t = 0; t < 4; t++) {
        int idx = tid + t * 256;
        int r = idx >> 3, c4 = (idx & 7) * 4;
        cp_async16(sA + (r * 36 + c4) * 4, g_xc + (size_t)ls[r] * H_DIM + k0 + c4);
    }
#pragma unroll
    for (int t = 0; t < 2; t++) {
        int idx = tid + t * 256;
        int r = idx >> 3, c4 = (idx & 7) * 4;
        cp_async16(sB1 + (r * 36 + c4) * 4, w1e + (size_t)r * H_DIM + k0 + c4);
        cp_async16(sB3 + (r * 36 + c4) * 4, w3e + (size_t)r * H_DIM + k0 + c4);
    }
}

__global__ __launch_bounds__(256, 2) void mlp1_kernel(
        const float* __restrict__ w1, const float* __restrict__ w3) {
    __shared__ int   ls[128];
    __shared__ float ws[128];

    int tidx = blockIdx.y;
    if (tidx >= g_ntiles) return;
    int e   = g_te[tidx];
    int m0  = g_tm[tidx];
    int cnt = g_cnt[e];
    int off = g_off[e];
    int f0  = blockIdx.x * 64;

    int tid = threadIdx.x, lane = tid & 31, wid = tid >> 5;
    int wm = wid >> 2, wn = wid & 3;          // 2(M) x 4(N)
    uint32_t sbase = smem_u32(dynsm);

    if (tid < 128) {
        int gm = m0 + tid;
        ls[tid] = (gm < cnt) ? g_list[e * T_TOK + gm] : 0;
        ws[tid] = (gm < cnt) ? g_wgt [e * T_TOK + gm] : 0.f;
    }
    __syncthreads();

    // per-lane ldmatrix offsets (bytes, within a stage)
    int lrow = lane & 7, lt = lane >> 3;
    uint32_t aoff[4], boff[2];
#pragma unroll
    for (int mt = 0; mt < 4; mt++)
        aoff[mt] = ((wm * 64 + mt * 16 + (lt & 1) * 8 + lrow) * 36 + (lt >> 1) * 4) * 4;
#pragma unroll
    for (int nt = 0; nt < 2; nt++)
        boff[nt] = ((wn * 16 + nt * 8 + lrow) * 36 + lt * 4) * 4;

    float accG[4][2][4], accU[4][2][4];
#pragma unroll
    for (int i = 0; i < 4; i++)
#pragma unroll
        for (int j = 0; j < 2; j++)
#pragma unroll
            for (int k = 0; k < 4; k++) { accG[i][j][k] = 0.f; accU[i][j][k] = 0.f; }

    const float* w1e = w1 + ((size_t)e * F_DIM + f0) * H_DIM;
    const float* w3e = w3 + ((size_t)e * F_DIM + f0) * H_DIM;

    const int NT = H_DIM / 32;   // 32
#pragma unroll
    for (int s = 0; s < STAGES - 1; s++) {
        load1(sbase, s, s * 32, w1e, w3e, ls, tid);
        CP_COMMIT();
    }

    int cbuf = 0, pbuf = STAGES - 1;
    for (int kt = 0; kt < NT; kt++) {
        CP_WAIT(STAGES - 2);
        __syncthreads();
        int nxt = kt + STAGES - 1;
        if (nxt < NT) load1(sbase, pbuf, nxt * 32, w1e, w3e, ls, tid);
        CP_COMMIT();
        if (++pbuf == STAGES) pbuf = 0;

        uint32_t sA  = sbase + (uint32_t)cbuf * S1_TOT * 4;
        uint32_t sB1 = sA + S1_A * 4;
        uint32_t sB3 = sB1 + S1_B * 4;
        if (++cbuf == STAGES) cbuf = 0;

#pragma unroll
        for (int p = 0; p < 2; p++) {           // two k16 halves per chunk
            uint32_t b1f[2][4], b3f[2][4];
#pragma unroll
            for (int nt = 0; nt < 2; nt++) {
                ldsm_x4(sB1 + boff[nt] + p * 64, b1f[nt]);
                ldsm_x4(sB3 + boff[nt] + p * 64, b3f[nt]);
#pragma unroll
                for (int j = 0; j < 4; j++) {
                    b1f[nt][j] = cvt_frag(b1f[nt][j]);
                    b3f[nt][j] = cvt_frag(b3f[nt][j]);
                }
            }
#pragma unroll
            for (int kq = 0; kq < 2; kq++) {
#pragma unroll
                for (int mt = 0; mt < 4; mt++) {
                    uint32_t af[4];
                    ldsm_x4(sA + aoff[mt] + (p * 2 + kq) * 32, af);
#pragma unroll
                    for (int nt = 0; nt < 2; nt++) {
                        mma_tf32(accG[mt][nt], af, b1f[nt] + kq * 2);
                        mma_tf32(accU[mt][nt], af, b3f[nt] + kq * 2);
                    }
                }
            }
        }
    }

    // epilogue: act = tf32( weight * gelu(G) * U )
#pragma unroll
    for (int mt = 0; mt < 4; mt++) {
        int rbase = wm * 64 + mt * 16 + (lane >> 2);
#pragma unroll
        for (int half = 0; half < 2; half++) {
            int m = rbase + half * 8;
            if (m0 + m >= cnt) continue;
            float wgt = ws[m];
            size_t rowoff = (size_t)(off + m0 + m) * F_DIM;
#pragma unroll
            for (int nt = 0; nt < 2; nt++) {
                int col = f0 + wn * 16 + nt * 8 + (lane & 3) * 2;
                float2 o;
                o.x = to_tf32(wgt * accU[mt][nt][half*2+0] * gelu_exact(accG[mt][nt][half*2+0]));
                o.y = to_tf32(wgt * accU[mt][nt][half*2+1] * gelu_exact(accG[mt][nt][half*2+1]));
                *reinterpret_cast<float2*>(&g_act[rowoff + col]) = o;
            }
        }
    }
}

// ---------------- GEMM2: out += act @ W2^T.  M=128 N=128, warps 2(M)x4(N), warp 64x32,
// split-K across gridDim.z (each kpart sums F/KSPLIT2; atomicAdd merges) ----------------
#define S2_A   4608                 // 128*36 floats
#define S2_B   4608                 // 128*36 floats
#define S2_TOT (S2_A + S2_B)        // 9216 floats

__device__ __forceinline__ void load2(uint32_t sbase, int buf, int k0,
                                      const float* __restrict__ arow,
                                      const float* __restrict__ w2e, int tid) {
    uint32_t sA = sbase + (uint32_t)buf * S2_TOT * 4;
    uint32_t sB = sA + S2_A * 4;
#pragma unroll
    for (int t = 0; t < 4; t++) {
        int idx = tid + t * 256;
        int r = idx >> 3, c4 = (idx & 7) * 4;
        cp_async16(sA + (r * 36 + c4) * 4, arow + (size_t)r * F_DIM + k0 + c4);
        cp_async16(sB + (r * 36 + c4) * 4, w2e  + (size_t)r * F_DIM + k0 + c4);
    }
}

__global__ __launch_bounds__(256, 2) void mlp2_kernel(
        const float* __restrict__ w2, float* __restrict__ out) {
    __shared__ int ls[128];

    int tidx = blockIdx.y;
    if (tidx >= g_ntiles) return;
    int e   = g_te[tidx];
    int m0  = g_tm[tidx];
    int cnt = g_cnt[e];
    int off = g_off[e];
    int h0  = blockIdx.x * 128;
    int kp  = blockIdx.z;                      // split-K partition
    int kbase = kp * (F_DIM / KSPLIT2);        // 0 or 2048

    int tid = threadIdx.x, lane = tid & 31, wid = tid >> 5;
    int wm = wid >> 2, wn = wid & 3;          // 2(M) x 4(N), warp tile 64 x 32
    uint32_t sbase = smem_u32(dynsm);

    if (tid < 128) {
        int gm = m0 + tid;
        ls[tid] = (gm < cnt) ? g_list[e * T_TOK + gm] : 0;
    }
    __syncthreads();

    int lrow = lane & 7, lt = lane >> 3;
    uint32_t aoff[4], boff[4];
#pragma unroll
    for (int mt = 0; mt < 4; mt++)
        aoff[mt] = ((wm * 64 + mt * 16 + (lt & 1) * 8 + lrow) * 36 + (lt >> 1) * 4) * 4;
#pragma unroll
    for (int nt = 0; nt < 4; nt++)
        boff[nt] = ((wn * 32 + nt * 8 + lrow) * 36 + lt * 4) * 4;

    float acc[4][4][4];
#pragma unroll
    for (int i = 0; i < 4; i++)
#pragma unroll
        for (int j = 0; j < 4; j++)
#pragma unroll
            for (int k = 0; k < 4; k++) acc[i][j][k] = 0.f;

    const float* w2e  = w2 + ((size_t)e * H_DIM + h0) * F_DIM + kbase;
    const float* arow = g_act + (size_t)(off + m0) * F_DIM + kbase;

    const int NT = F_DIM / (32 * KSPLIT2);   // 64
#pragma unroll
    for (int s = 0; s < STAGES - 1; s++) {
        load2(sbase, s, s * 32, arow, w2e, tid);
        CP_COMMIT();
    }

    int cbuf = 0, pbuf = STAGES - 1;
    for (int kt = 0; kt < NT; kt++) {
        CP_WAIT(STAGES - 2);
        __syncthreads();
        int nxt = kt + STAGES - 1;
        if (nxt < NT) load2(sbase, pbuf, nxt * 32, arow, w2e, tid);
        CP_COMMIT();
        if (++pbuf == STAGES) pbuf = 0;

        uint32_t sA = sbase + (uint32_t)cbuf * S2_TOT * 4;
        uint32_t sB = sA + S2_A * 4;
        if (++cbuf == STAGES) cbuf = 0;

#pragma unroll
        for (int p = 0; p < 2; p++) {
            uint32_t bf[4][4];
#pragma unroll
            for (int nt = 0; nt < 4; nt++) {
                ldsm_x4(sB + boff[nt] + p * 64, bf[nt]);
#pragma unroll
                for (int j = 0; j < 4; j++) bf[nt][j] = cvt_frag(bf[nt][j]);
            }
#pragma unroll
            for (int kq = 0; kq < 2; kq++) {
#pragma unroll
                for (int mt = 0; mt < 4; mt++) {
                    uint32_t af[4];
                    ldsm_x4(sA + aoff[mt] + (p * 2 + kq) * 32, af);
#pragma unroll
                    for (int nt = 0; nt < 4; nt++)
                        mma_tf32(acc[mt][nt], af, bf[nt] + kq * 2);
                }
            }
        }
    }

    // epilogue: atomicAdd into out (commutative fp32 adds; <=4 contributions/element)
#pragma unroll
    for (int mt = 0; mt < 4; mt++) {
        int rbase = wm * 64 + mt * 16 + (lane >> 2);
#pragma unroll
        for (int half = 0; half < 2; half++) {
            int m = rbase + half * 8;
            if (m0 + m >= cnt) continue;
            int token = ls[m];
#pragma unroll
            for (int nt = 0; nt < 4; nt++) {
                int h = h0 + wn * 32 + nt * 8 + (lane & 3) * 2;
                atomicAdd(&out[(size_t)token * H_DIM + h],     acc[mt][nt][half * 2 + 0]);
                atomicAdd(&out[(size_t)token * H_DIM + h + 1], acc[mt][nt][half * 2 + 1]);
            }
        }
    }
}

// ---------------- launch ----------------
extern "C" void kernel_launch(void* const* d_in, const int* in_sizes, int n_in,
                              void* d_out, int out_size) {
    const float* x  = (const float*)d_in[0];   // [T, H]
    const float* gw = (const float*)d_in[1];   // [E, H]
    const float* w1 = (const float*)d_in[2];   // [E, F, H]
    const float* w2 = (const float*)d_in[3];   // [E, H, F]
    const float* w3 = (const float*)d_in[4];   // [E, F, H]
    float* out = (float*)d_out;                // [T, H]

    const int smem1 = STAGES * S1_TOT * 4;   // 110592 B
    const int smem2 = STAGES * S2_TOT * 4;   // 110592 B
    cudaFuncSetAttribute(mlp1_kernel, cudaFuncAttributeMaxDynamicSharedMemorySize, smem1);
    cudaFuncSetAttribute(mlp2_kernel, cudaFuncAttributeMaxDynamicSharedMemorySize, smem2);

    // router also zeroes out and writes rounded x -> g_xc (float4-vectorized)
    router_kernel<<<512, 128>>>((const float4*)x, (const float4*)gw, (float4*)out);
    build_kernel<<<1, 256>>>();                 // also builds packed tile list

    dim3 g1(F_DIM / 64, MAX_TILES, 1);          // (64, 40)
    mlp1_kernel<<<g1, 256, smem1>>>(w1, w3);
    dim3 g2(H_DIM / 128, MAX_TILES, KSPLIT2);   // (8, 40, 2)
    mlp2_kernel<<<g2, 256, smem2>>>(w2, out);
}